// round 1
// baseline (speedup 1.0000x reference)
#include <cuda_runtime.h>
#include <cmath>
#include <complex>
#include <algorithm>

// ----------------------------------------------------------------------------
// Problem constants
// ----------------------------------------------------------------------------
#define NNODES   50000
#define C_DIM    128
#define M_DIM    9
#define B_NODES  8            // nodes per block
#define THREADS  256

// Wigner-3j tables (alpha folded in), passed by value as kernel arg (460 B).
struct W3J {
    float w220[25];   // [i(5)][j(5)]       (k dim == 1), alpha = 1
    float w121[45];   // [i(3)][j(5)][k(3)] alpha = sqrt(3)
    float w112[45];   // [i(3)][j(3)][k(5)] alpha = sqrt(5)
};

// ----------------------------------------------------------------------------
// Host-side Wigner 3j (literal translation of the reference, double precision)
// ----------------------------------------------------------------------------
namespace hw3j {
typedef std::complex<double> cd;

static inline double fact(int n) { double r = 1.0; for (int i = 2; i <= n; ++i) r *= (double)i; return r; }

static double su2_cg(int j1, int m1, int j2, int m2, int j3, int m3) {
    if (m1 + m2 != m3) return 0.0;
    int vmin = std::max(std::max(-j1 + j2 + m3, -j1 + m1), 0);
    int vmax = std::min(std::min(j2 + j3 + m1, j3 - j1 + j2), j3 + m3);
    double pref = std::sqrt((2.0 * j3 + 1.0)
        * fact(j3 + j1 - j2) * fact(j3 - j1 + j2) * fact(j1 + j2 - j3) / fact(j1 + j2 + j3 + 1)
        * fact(j3 + m3) * fact(j3 - m3)
        / (fact(j1 - m1) * fact(j1 + m1) * fact(j2 - m2) * fact(j2 + m2)));
    double s = 0.0;
    for (int v = vmin; v <= vmax; ++v) {
        double sgn = ((v + j2 + m2) & 1) ? -1.0 : 1.0;
        s += sgn / fact(v) * fact(j2 + j3 + m1 - v) * fact(j1 - m1 + v)
             / (fact(j3 - j1 + j2 - v) * fact(j3 + m3 - v) * fact(v + j1 - j2 - m3));
    }
    return pref * s;
}

static void qmat(int l, cd q[5][5]) {
    for (int a = 0; a < 5; ++a) for (int b = 0; b < 5; ++b) q[a][b] = cd(0, 0);
    const double is2 = 1.0 / std::sqrt(2.0);
    for (int m = -l; m < 0; ++m) {
        q[l + m][l - m] = cd(is2, 0.0);     // col l + |m|
        q[l + m][l + m] = cd(0.0, -is2);    // col l - |m|
    }
    q[l][l] = cd(1.0, 0.0);
    for (int m = 1; m <= l; ++m) {
        double sg = (m & 1) ? -1.0 : 1.0;
        q[l + m][l + m] = cd(sg * is2, 0.0);
        q[l + m][l - m] = cd(0.0, sg * is2);
    }
    cd ph;
    switch (l & 3) {  // (-1j)^l
        case 0: ph = cd( 1,  0); break;
        case 1: ph = cd( 0, -1); break;
        case 2: ph = cd(-1,  0); break;
        default: ph = cd(0,  1); break;
    }
    for (int a = 0; a < 2 * l + 1; ++a) for (int b = 0; b < 2 * l + 1; ++b) q[a][b] *= ph;
}

static void wig3j(int l1, int l2, int l3, float* out) {
    const int d1 = 2 * l1 + 1, d2 = 2 * l2 + 1, d3 = 2 * l3 + 1;
    cd Q1[5][5], Q2[5][5], Q3[5][5];
    qmat(l1, Q1); qmat(l2, Q2); qmat(l3, Q3);
    static cd Csu2[5][5][5];
    for (int i = 0; i < d1; ++i)
        for (int k = 0; k < d2; ++k)
            for (int n = 0; n < d3; ++n)
                Csu2[i][k][n] = cd(su2_cg(l1, i - l1, l2, k - l2, l3, n - l3), 0.0);
    static double Cr[5][5][5];
    double nrm = 0.0;
    for (int j = 0; j < d1; ++j)
        for (int ll = 0; ll < d2; ++ll)
            for (int m = 0; m < d3; ++m) {
                cd acc(0, 0);
                for (int i = 0; i < d1; ++i)
                    for (int k = 0; k < d2; ++k)
                        for (int n = 0; n < d3; ++n)
                            acc += Q1[i][j] * Q2[k][ll] * std::conj(Q3[n][m]) * Csu2[i][k][n];
                Cr[j][ll][m] = acc.real();
                nrm += acc.real() * acc.real();
            }
    nrm = std::sqrt(nrm);
    int idx = 0;
    for (int j = 0; j < d1; ++j)
        for (int ll = 0; ll < d2; ++ll)
            for (int m = 0; m < d3; ++m)
                out[idx++] = (float)(Cr[j][ll][m] / nrm);
}

static void build(W3J& P) {
    float c220[25], c121[45], c112[45];
    wig3j(2, 2, 0, c220);
    wig3j(1, 2, 1, c121);
    wig3j(1, 1, 2, c112);
    const float a220 = 1.0f, a121 = std::sqrt(3.0f), a112 = std::sqrt(5.0f);
    for (int i = 0; i < 25; ++i) P.w220[i] = a220 * c220[i];
    for (int i = 0; i < 45; ++i) P.w121[i] = a121 * c121[i];
    for (int i = 0; i < 45; ++i) P.w112[i] = a112 * c112[i];
}
} // namespace hw3j

// ----------------------------------------------------------------------------
// Fused kernel: linear(left) + linear(right) -> CG tensor product -> linear(final)
// Each thread owns one output channel d; 8 nodes per block staged in smem.
// ----------------------------------------------------------------------------
__global__ __launch_bounds__(THREADS, 2)
void b2i_fused_kernel(const float* __restrict__ x,
                      const float* __restrict__ Wl, const float* __restrict__ bl,
                      const float* __restrict__ Wr, const float* __restrict__ br,
                      const float* __restrict__ Wf, const float* __restrict__ bf,
                      float* __restrict__ out, const W3J P)
{
    extern __shared__ float smem[];
    float* sx = smem;                          // [8][9][128]
    float* st = smem + B_NODES * M_DIM * C_DIM;

    const int tid = threadIdx.x;
    const int d   = tid & 127;                 // channel owned by this thread
    const int nh  = tid >> 7;                  // node-half: 0 or 1
    const size_t node0 = (size_t)blockIdx.x * B_NODES;

    // ---- load x tile (coalesced float4 copy) ----
    {
        const float4* gx = reinterpret_cast<const float4*>(x + node0 * M_DIM * C_DIM);
        float4* s4 = reinterpret_cast<float4*>(sx);
        #pragma unroll
        for (int i = 0; i < (B_NODES * M_DIM * C_DIM / 4) / THREADS; ++i)
            s4[tid + i * THREADS] = gx[tid + i * THREADS];
    }
    __syncthreads();

    // ---- stage A: left/right per-degree linears into registers ----
    float yl[4][M_DIM], yr[4][M_DIM];
    #pragma unroll
    for (int n = 0; n < 4; ++n) {
        #pragma unroll
        for (int m = 0; m < M_DIM; ++m) { yl[n][m] = 0.f; yr[n][m] = 0.f; }
    }

    #pragma unroll
    for (int l = 0; l < 3; ++l) {
        const int base = l * l, msz = 2 * l + 1;
        const float4* wa = reinterpret_cast<const float4*>(Wl + (size_t)(l * 128 + d) * 128);
        const float4* wb = reinterpret_cast<const float4*>(Wr + (size_t)(l * 128 + d) * 128);
        for (int c4 = 0; c4 < 32; ++c4) {
            const float4 a = __ldg(wa + c4);
            const float4 b = __ldg(wb + c4);
            #pragma unroll
            for (int n = 0; n < 4; ++n) {
                const int node = nh * 4 + n;
                #pragma unroll
                for (int mm = 0; mm < msz; ++mm) {
                    // warp-uniform address -> broadcast LDS.128, conflict-free
                    const float4 xv = *reinterpret_cast<const float4*>(
                        sx + (node * M_DIM + base + mm) * C_DIM + c4 * 4);
                    float& al = yl[n][base + mm];
                    float& ar = yr[n][base + mm];
                    al = fmaf(xv.x, a.x, fmaf(xv.y, a.y, fmaf(xv.z, a.z, fmaf(xv.w, a.w, al))));
                    ar = fmaf(xv.x, b.x, fmaf(xv.y, b.y, fmaf(xv.z, b.z, fmaf(xv.w, b.w, ar))));
                }
            }
        }
    }

    const float blv = bl[d];
    const float brv = br[d];

    // ---- stage B: bias (l=0 only) + channel-wise CG tensor product -> smem ----
    #pragma unroll
    for (int n = 0; n < 4; ++n) {
        const int node = nh * 4 + n;
        float L[M_DIM], R[M_DIM];
        #pragma unroll
        for (int m = 0; m < M_DIM; ++m) { L[m] = yl[n][m]; R[m] = yr[n][m]; }
        L[0] += blv; R[0] += brv;

        float t[M_DIM];
        // (2,2,0): out m=0
        {
            float s = 0.f;
            #pragma unroll
            for (int i = 0; i < 5; ++i) {
                #pragma unroll
                for (int j = 0; j < 5; ++j)
                    s = fmaf(P.w220[i * 5 + j], L[4 + i] * R[4 + j], s);
            }
            t[0] = s;
        }
        // (1,2,1): out m=1..3
        #pragma unroll
        for (int k = 0; k < 3; ++k) {
            float s = 0.f;
            #pragma unroll
            for (int i = 0; i < 3; ++i) {
                #pragma unroll
                for (int j = 0; j < 5; ++j)
                    s = fmaf(P.w121[(i * 5 + j) * 3 + k], L[1 + i] * R[4 + j], s);
            }
            t[1 + k] = s;
        }
        // (1,1,2): out m=4..8
        #pragma unroll
        for (int k = 0; k < 5; ++k) {
            float s = 0.f;
            #pragma unroll
            for (int i = 0; i < 3; ++i) {
                #pragma unroll
                for (int j = 0; j < 3; ++j)
                    s = fmaf(P.w112[(i * 3 + j) * 5 + k], L[1 + i] * R[1 + j], s);
            }
            t[4 + k] = s;
        }
        #pragma unroll
        for (int m = 0; m < M_DIM; ++m)
            st[(node * M_DIM + m) * C_DIM + d] = t[m];
    }
    __syncthreads();

    // ---- stage C: final per-degree linear + bias, write out ----
    float o[4][M_DIM];
    #pragma unroll
    for (int n = 0; n < 4; ++n) {
        #pragma unroll
        for (int m = 0; m < M_DIM; ++m) o[n][m] = 0.f;
    }

    #pragma unroll
    for (int l = 0; l < 3; ++l) {
        const int base = l * l, msz = 2 * l + 1;
        const float4* wc = reinterpret_cast<const float4*>(Wf + (size_t)(l * 128 + d) * 128);
        for (int c4 = 0; c4 < 32; ++c4) {
            const float4 a = __ldg(wc + c4);
            #pragma unroll
            for (int n = 0; n < 4; ++n) {
                const int node = nh * 4 + n;
                #pragma unroll
                for (int mm = 0; mm < msz; ++mm) {
                    const float4 xv = *reinterpret_cast<const float4*>(
                        st + (node * M_DIM + base + mm) * C_DIM + c4 * 4);
                    float& ac = o[n][base + mm];
                    ac = fmaf(xv.x, a.x, fmaf(xv.y, a.y, fmaf(xv.z, a.z, fmaf(xv.w, a.w, ac))));
                }
            }
        }
    }

    const float bfv = bf[d];
    #pragma unroll
    for (int n = 0; n < 4; ++n) {
        const int node = nh * 4 + n;
        o[n][0] += bfv;
        #pragma unroll
        for (int m = 0; m < M_DIM; ++m)
            out[(node0 + node) * M_DIM * C_DIM + m * C_DIM + d] = o[n][m];
    }
}

// ----------------------------------------------------------------------------
// Launch
// ----------------------------------------------------------------------------
extern "C" void kernel_launch(void* const* d_in, const int* in_sizes, int n_in,
                              void* d_out, int out_size)
{
    const float* x  = (const float*)d_in[0];
    const float* Wl = (const float*)d_in[1];
    const float* bl = (const float*)d_in[2];
    const float* Wr = (const float*)d_in[3];
    const float* br = (const float*)d_in[4];
    const float* Wf = (const float*)d_in[5];
    const float* bf = (const float*)d_in[6];
    float* out = (float*)d_out;

    W3J P;
    hw3j::build(P);   // cheap, deterministic, every call

    const int smem_bytes = 2 * B_NODES * M_DIM * C_DIM * (int)sizeof(float);  // 73728
    cudaFuncSetAttribute(b2i_fused_kernel, cudaFuncAttributeMaxDynamicSharedMemorySize, smem_bytes);

    b2i_fused_kernel<<<NNODES / B_NODES, THREADS, smem_bytes>>>(
        x, Wl, bl, Wr, br, Wf, bf, out, P);
}

// round 2
// speedup vs baseline: 1.0335x; 1.0335x over previous
#include <cuda_runtime.h>
#include <cmath>
#include <complex>
#include <algorithm>

// ----------------------------------------------------------------------------
// Problem constants
// ----------------------------------------------------------------------------
#define NNODES   50000
#define C_DIM    128
#define M_DIM    9
#define B_NODES  16           // nodes per block
#define THREADS  512

// Wigner-3j tables (alpha folded in), passed by value as kernel arg.
struct W3J {
    float w220[25];
    float w121[45];
    float w112[45];
};

// ----------------------------------------------------------------------------
// Host-side Wigner 3j (literal translation of the reference, double precision)
// ----------------------------------------------------------------------------
namespace hw3j {
typedef std::complex<double> cd;

static inline double fact(int n) { double r = 1.0; for (int i = 2; i <= n; ++i) r *= (double)i; return r; }

static double su2_cg(int j1, int m1, int j2, int m2, int j3, int m3) {
    if (m1 + m2 != m3) return 0.0;
    int vmin = std::max(std::max(-j1 + j2 + m3, -j1 + m1), 0);
    int vmax = std::min(std::min(j2 + j3 + m1, j3 - j1 + j2), j3 + m3);
    double pref = std::sqrt((2.0 * j3 + 1.0)
        * fact(j3 + j1 - j2) * fact(j3 - j1 + j2) * fact(j1 + j2 - j3) / fact(j1 + j2 + j3 + 1)
        * fact(j3 + m3) * fact(j3 - m3)
        / (fact(j1 - m1) * fact(j1 + m1) * fact(j2 - m2) * fact(j2 + m2)));
    double s = 0.0;
    for (int v = vmin; v <= vmax; ++v) {
        double sgn = ((v + j2 + m2) & 1) ? -1.0 : 1.0;
        s += sgn / fact(v) * fact(j2 + j3 + m1 - v) * fact(j1 - m1 + v)
             / (fact(j3 - j1 + j2 - v) * fact(j3 + m3 - v) * fact(v + j1 - j2 - m3));
    }
    return pref * s;
}

static void qmat(int l, cd q[5][5]) {
    for (int a = 0; a < 5; ++a) for (int b = 0; b < 5; ++b) q[a][b] = cd(0, 0);
    const double is2 = 1.0 / std::sqrt(2.0);
    for (int m = -l; m < 0; ++m) {
        q[l + m][l - m] = cd(is2, 0.0);
        q[l + m][l + m] = cd(0.0, -is2);
    }
    q[l][l] = cd(1.0, 0.0);
    for (int m = 1; m <= l; ++m) {
        double sg = (m & 1) ? -1.0 : 1.0;
        q[l + m][l + m] = cd(sg * is2, 0.0);
        q[l + m][l - m] = cd(0.0, sg * is2);
    }
    cd ph;
    switch (l & 3) {
        case 0: ph = cd( 1,  0); break;
        case 1: ph = cd( 0, -1); break;
        case 2: ph = cd(-1,  0); break;
        default: ph = cd(0,  1); break;
    }
    for (int a = 0; a < 2 * l + 1; ++a) for (int b = 0; b < 2 * l + 1; ++b) q[a][b] *= ph;
}

static void wig3j(int l1, int l2, int l3, float* out) {
    const int d1 = 2 * l1 + 1, d2 = 2 * l2 + 1, d3 = 2 * l3 + 1;
    cd Q1[5][5], Q2[5][5], Q3[5][5];
    qmat(l1, Q1); qmat(l2, Q2); qmat(l3, Q3);
    static cd Csu2[5][5][5];
    for (int i = 0; i < d1; ++i)
        for (int k = 0; k < d2; ++k)
            for (int n = 0; n < d3; ++n)
                Csu2[i][k][n] = cd(su2_cg(l1, i - l1, l2, k - l2, l3, n - l3), 0.0);
    static double Cr[5][5][5];
    double nrm = 0.0;
    for (int j = 0; j < d1; ++j)
        for (int ll = 0; ll < d2; ++ll)
            for (int m = 0; m < d3; ++m) {
                cd acc(0, 0);
                for (int i = 0; i < d1; ++i)
                    for (int k = 0; k < d2; ++k)
                        for (int n = 0; n < d3; ++n)
                            acc += Q1[i][j] * Q2[k][ll] * std::conj(Q3[n][m]) * Csu2[i][k][n];
                Cr[j][ll][m] = acc.real();
                nrm += acc.real() * acc.real();
            }
    nrm = std::sqrt(nrm);
    int idx = 0;
    for (int j = 0; j < d1; ++j)
        for (int ll = 0; ll < d2; ++ll)
            for (int m = 0; m < d3; ++m)
                out[idx++] = (float)(Cr[j][ll][m] / nrm);
}

static void build(W3J& P) {
    float c220[25], c121[45], c112[45];
    wig3j(2, 2, 0, c220);
    wig3j(1, 2, 1, c121);
    wig3j(1, 1, 2, c112);
    const float a121 = std::sqrt(3.0f), a112 = std::sqrt(5.0f);
    for (int i = 0; i < 25; ++i) P.w220[i] = c220[i];
    for (int i = 0; i < 45; ++i) P.w121[i] = a121 * c121[i];
    for (int i = 0; i < 45; ++i) P.w112[i] = a112 * c112[i];
}
} // namespace hw3j

// ----------------------------------------------------------------------------
// Packed fp32 helpers (Blackwell f32x2)
// ----------------------------------------------------------------------------
__device__ __forceinline__ void fma2(unsigned long long& acc,
                                     unsigned long long a, unsigned long long b) {
    asm("fma.rn.f32x2 %0, %1, %2, %0;" : "+l"(acc) : "l"(a), "l"(b));
}
__device__ __forceinline__ float f2lo(unsigned long long v) {
    return __uint_as_float((unsigned int)v);
}
__device__ __forceinline__ float f2hi(unsigned long long v) {
    return __uint_as_float((unsigned int)(v >> 32));
}

// Smem geometry (floats):
//  sx  : [16 nodes][9 m][128 c][2 dup]            = 36864 floats (reused as t-buffer)
//  sw  : weight staging, max(128*132, 64*260)     = 16896 floats
#define SX_FLOATS   (B_NODES * M_DIM * C_DIM * 2)
#define SWA_STRIDE  132      // stage A: [128 d][64 c x {Wl,Wr}] + pad4, stride%32==4
#define SWC_STRIDE  260      // stage C: [64 d2][128 c x {Wf[d2],Wf[d2+64]}] + pad4
#define SW_FLOATS   16896
#define SMEM_BYTES  ((SX_FLOATS + SW_FLOATS) * 4)

// ----------------------------------------------------------------------------
// Fused kernel
// ----------------------------------------------------------------------------
__global__ __launch_bounds__(THREADS, 1)
void b2i_fused_kernel(const float* __restrict__ x,
                      const float* __restrict__ Wl, const float* __restrict__ bl,
                      const float* __restrict__ Wr, const float* __restrict__ br,
                      const float* __restrict__ Wf, const float* __restrict__ bf,
                      float* __restrict__ out, const W3J P)
{
    extern __shared__ float smem[];
    float* sx = smem;                 // x (dup), later t (dup)
    float* sw = smem + SX_FLOATS;     // weight staging

    const int tid = threadIdx.x;
    const int d   = tid & 127;        // stage A/B channel
    const int ng  = tid >> 7;         // stage A/B node group (4 nodes)
    const size_t node0 = (size_t)blockIdx.x * B_NODES;

    // ---- load x tile into duplicated smem layout [node][m][c][2] ----
    {
        const float2* gx2 = reinterpret_cast<const float2*>(x + node0 * M_DIM * C_DIM);
        #pragma unroll
        for (int i = 0; i < (B_NODES * M_DIM * C_DIM / 2) / THREADS; ++i) {
            const int q = tid + i * THREADS;      // float2 index
            const float2 g = gx2[q];
            const int row = q >> 6;               // node*9+m
            const int cp  = q & 63;               // c pair
            float4 v; v.x = g.x; v.y = g.x; v.z = g.y; v.w = g.y;
            *reinterpret_cast<float4*>(sx + row * 256 + cp * 4) = v;
        }
    }

    const float blv = bl[d];
    const float brv = br[d];

    // =========================================================================
    // Stage A: yl/yr = per-degree linears, packed {left,right} in f32x2
    // =========================================================================
    unsigned long long acc[4][M_DIM];
    #pragma unroll
    for (int n = 0; n < 4; ++n)
        #pragma unroll
        for (int m = 0; m < M_DIM; ++m) acc[n][m] = 0ULL;

    #pragma unroll
    for (int l = 0; l < 3; ++l) {
        const int base = l * l, msz = 2 * l + 1;
        #pragma unroll
        for (int ch = 0; ch < 2; ++ch) {              // two 64-channel chunks
            if (!(l == 0 && ch == 0)) __syncthreads();  // prev chunk compute done
            // ---- stage Wl/Wr chunk interleaved: sw[d][cl*2+{0,1}] ----
            {
                const int drow = tid >> 2;
                const int quad = tid & 3;
                const float* gl = Wl + (size_t)(l * 128 + drow) * 128 + ch * 64 + quad * 16;
                const float* gr = Wr + (size_t)(l * 128 + drow) * 128 + ch * 64 + quad * 16;
                #pragma unroll
                for (int k4 = 0; k4 < 4; ++k4) {
                    const float4 a = __ldg(reinterpret_cast<const float4*>(gl + k4 * 4));
                    const float4 b = __ldg(reinterpret_cast<const float4*>(gr + k4 * 4));
                    const int cl = quad * 16 + k4 * 4;
                    float2* p = reinterpret_cast<float2*>(sw + drow * SWA_STRIDE + cl * 2);
                    p[0] = make_float2(a.x, b.x);
                    p[1] = make_float2(a.y, b.y);
                    p[2] = make_float2(a.z, b.z);
                    p[3] = make_float2(a.w, b.w);
                }
            }
            __syncthreads();
            // ---- compute: acc[n][base+m] += {x,x} * {Wl,Wr} ----
            const float* swr = sw + d * SWA_STRIDE;
            for (int c2 = 0; c2 < 32; ++c2) {
                const ulonglong2 w = *reinterpret_cast<const ulonglong2*>(swr + c2 * 4);
                #pragma unroll
                for (int n = 0; n < 4; ++n) {
                    const float* xb = sx + ((ng * 4 + n) * M_DIM + base) * 256 + ch * 128 + c2 * 4;
                    #pragma unroll
                    for (int mm = 0; mm < msz; ++mm) {
                        const ulonglong2 xx = *reinterpret_cast<const ulonglong2*>(xb + mm * 256);
                        fma2(acc[n][base + mm], xx.x, w.x);
                        fma2(acc[n][base + mm], xx.y, w.y);
                    }
                }
            }
        }
    }

    // =========================================================================
    // Stage B: bias + CG tensor product, write t (duplicated) back into sx
    // =========================================================================
    __syncthreads();   // all stage-A reads of sx complete before overwrite
    #pragma unroll
    for (int n = 0; n < 4; ++n) {
        const int node = ng * 4 + n;
        float L[M_DIM], R[M_DIM];
        #pragma unroll
        for (int m = 0; m < M_DIM; ++m) { L[m] = f2lo(acc[n][m]); R[m] = f2hi(acc[n][m]); }
        L[0] += blv; R[0] += brv;

        float t[M_DIM];
        {   // (2,2,0)
            float s = 0.f;
            #pragma unroll
            for (int i = 0; i < 5; ++i)
                #pragma unroll
                for (int j = 0; j < 5; ++j)
                    s = fmaf(P.w220[i * 5 + j], L[4 + i] * R[4 + j], s);
            t[0] = s;
        }
        #pragma unroll
        for (int k = 0; k < 3; ++k) {   // (1,2,1)
            float s = 0.f;
            #pragma unroll
            for (int i = 0; i < 3; ++i)
                #pragma unroll
                for (int j = 0; j < 5; ++j)
                    s = fmaf(P.w121[(i * 5 + j) * 3 + k], L[1 + i] * R[4 + j], s);
            t[1 + k] = s;
        }
        #pragma unroll
        for (int k = 0; k < 5; ++k) {   // (1,1,2)
            float s = 0.f;
            #pragma unroll
            for (int i = 0; i < 3; ++i)
                #pragma unroll
                for (int j = 0; j < 3; ++j)
                    s = fmaf(P.w112[(i * 3 + j) * 5 + k], L[1 + i] * R[1 + j], s);
            t[4 + k] = s;
        }
        #pragma unroll
        for (int m = 0; m < M_DIM; ++m)
            *reinterpret_cast<float2*>(sx + (node * M_DIM + m) * 256 + d * 2)
                = make_float2(t[m], t[m]);
    }

    // =========================================================================
    // Stage C: final linear, packed {channel d2, channel d2+64} in f32x2
    // =========================================================================
    const int d2  = tid & 63;
    const int ng2 = tid >> 6;          // 8 groups x 2 nodes

    unsigned long long accc[2][M_DIM];
    #pragma unroll
    for (int n = 0; n < 2; ++n)
        #pragma unroll
        for (int m = 0; m < M_DIM; ++m) accc[n][m] = 0ULL;

    #pragma unroll
    for (int l = 0; l < 3; ++l) {
        const int base = l * l, msz = 2 * l + 1;
        __syncthreads();   // t writes done (l=0) / prev-l compute done reading sw
        // ---- stage Wf[l] pair-interleaved: sw[d2][c*2+{0,1}] = {Wf[d2][c], Wf[d2+64][c]} ----
        {
            const int drow = tid >> 3;       // 0..63
            const int oct  = tid & 7;
            const float* glo = Wf + (size_t)(l * 128 + drow) * 128 + oct * 16;
            const float* ghi = Wf + (size_t)(l * 128 + drow + 64) * 128 + oct * 16;
            #pragma unroll
            for (int k4 = 0; k4 < 4; ++k4) {
                const float4 a = __ldg(reinterpret_cast<const float4*>(glo + k4 * 4));
                const float4 b = __ldg(reinterpret_cast<const float4*>(ghi + k4 * 4));
                const int cl = oct * 16 + k4 * 4;
                float2* p = reinterpret_cast<float2*>(sw + drow * SWC_STRIDE + cl * 2);
                p[0] = make_float2(a.x, b.x);
                p[1] = make_float2(a.y, b.y);
                p[2] = make_float2(a.z, b.z);
                p[3] = make_float2(a.w, b.w);
            }
        }
        __syncthreads();
        // ---- compute ----
        const float* swr = sw + d2 * SWC_STRIDE;
        for (int c2 = 0; c2 < 64; ++c2) {
            const ulonglong2 w = *reinterpret_cast<const ulonglong2*>(swr + c2 * 4);
            #pragma unroll
            for (int n = 0; n < 2; ++n) {
                const float* tb = sx + ((ng2 * 2 + n) * M_DIM + base) * 256 + c2 * 4;
                #pragma unroll
                for (int mm = 0; mm < msz; ++mm) {
                    const ulonglong2 xx = *reinterpret_cast<const ulonglong2*>(tb + mm * 256);
                    fma2(accc[n][base + mm], xx.x, w.x);
                    fma2(accc[n][base + mm], xx.y, w.y);
                }
            }
        }
    }

    // ---- bias + write out ----
    const float bflo = bf[d2];
    const float bfhi = bf[d2 + 64];
    #pragma unroll
    for (int n = 0; n < 2; ++n) {
        const size_t node = node0 + ng2 * 2 + n;
        #pragma unroll
        for (int m = 0; m < M_DIM; ++m) {
            float olo = f2lo(accc[n][m]);
            float ohi = f2hi(accc[n][m]);
            if (m == 0) { olo += bflo; ohi += bfhi; }
            out[(node * M_DIM + m) * C_DIM + d2]      = olo;
            out[(node * M_DIM + m) * C_DIM + d2 + 64] = ohi;
        }
    }
}

// ----------------------------------------------------------------------------
// Launch
// ----------------------------------------------------------------------------
extern "C" void kernel_launch(void* const* d_in, const int* in_sizes, int n_in,
                              void* d_out, int out_size)
{
    const float* x  = (const float*)d_in[0];
    const float* Wl = (const float*)d_in[1];
    const float* bl = (const float*)d_in[2];
    const float* Wr = (const float*)d_in[3];
    const float* br = (const float*)d_in[4];
    const float* Wf = (const float*)d_in[5];
    const float* bf = (const float*)d_in[6];
    float* out = (float*)d_out;

    W3J P;
    hw3j::build(P);

    cudaFuncSetAttribute(b2i_fused_kernel, cudaFuncAttributeMaxDynamicSharedMemorySize, SMEM_BYTES);

    b2i_fused_kernel<<<NNODES / B_NODES, THREADS, SMEM_BYTES>>>(
        x, Wl, bl, Wr, br, Wf, bf, out, P);
}